// round 3
// baseline (speedup 1.0000x reference)
#include <cuda_runtime.h>
#include <cuda_bf16.h>

// Problem constants (fixed by setup_inputs)
#define NA   1024      // anchors
#define NB   8192      // database rows (out1/out2)
#define DIM  128       // feature dim
#define KSEL 64        // top-K
#define BM   64
#define BN   64
#define KC   64        // K-chunk (two chunks cover DIM=128)
#define PAD  68        // padded row stride in floats (16B aligned, conflict-free for LDS.128)

// Scratch (static device allocations are allowed)
__device__ float g_dist[2][NA][NB];     // 64 MB
__device__ int   g_neg[2][NA][KSEL];
__device__ float g_partial[NA];

// ---------- packed f32x2 helpers ----------
__device__ __forceinline__ unsigned long long f2add(unsigned long long a, unsigned long long b) {
    unsigned long long d;
    asm("add.rn.f32x2 %0, %1, %2;" : "=l"(d) : "l"(a), "l"(b));
    return d;
}
__device__ __forceinline__ unsigned long long f2abs(unsigned long long a) {
    return a & 0x7fffffff7fffffffULL;   // clear both sign bits (LOP3, alu pipe)
}

// ---------- pass 1: L1 cdist (gathered anchors vs database) ----------
// side 0: A=out1 gathered by anchor1, B=out2.  side 1: A=out2 by anchor2, B=out1.
__global__ void __launch_bounds__(256, 3)
cdist_kernel(const float* __restrict__ out1, const float* __restrict__ out2,
             const int* __restrict__ a1, const int* __restrict__ a2)
{
    __shared__ float As[BM][PAD];
    __shared__ float Bs[BN][PAD];

    const int side = blockIdx.z;
    const float* A = side ? out2 : out1;
    const float* B = side ? out1 : out2;
    const int* anch = side ? a2 : a1;

    const int tid = threadIdx.x;
    const int bm = blockIdx.y * BM;
    const int bn = blockIdx.x * BN;

    const int tx = tid & 15;   // N direction
    const int ty = tid >> 4;   // M direction

    unsigned long long acc[4][4];
#pragma unroll
    for (int m = 0; m < 4; m++)
#pragma unroll
        for (int n = 0; n < 4; n++) acc[m][n] = 0ULL;

    for (int kc = 0; kc < DIM; kc += KC) {
        // Load A tile chunk (gather): 64 rows x 64 cols = 16 float4/row
        for (int u = tid; u < BM * 16; u += 256) {
            int r = u >> 4, kq = u & 15;
            int ga = __ldg(&anch[bm + r]);
            float4 v = *(const float4*)&A[(long long)ga * DIM + kc + kq * 4];
            *(float4*)&As[r][kq * 4] = v;
        }
        // Load B tile chunk, negated
        for (int u = tid; u < BN * 16; u += 256) {
            int r = u >> 4, kq = u & 15;
            float4 v = *(const float4*)&B[(long long)(bn + r) * DIM + kc + kq * 4];
            v.x = -v.x; v.y = -v.y; v.z = -v.z; v.w = -v.w;
            *(float4*)&Bs[r][kq * 4] = v;
        }
        __syncthreads();

#pragma unroll 4
        for (int kk = 0; kk < KC; kk += 4) {
            ulonglong2 av[4], bv[4];
#pragma unroll
            for (int m = 0; m < 4; m++) av[m] = *(const ulonglong2*)&As[ty + 16 * m][kk];
#pragma unroll
            for (int n = 0; n < 4; n++) bv[n] = *(const ulonglong2*)&Bs[tx + 16 * n][kk];
#pragma unroll
            for (int m = 0; m < 4; m++)
#pragma unroll
                for (int n = 0; n < 4; n++) {
                    acc[m][n] = f2add(acc[m][n], f2abs(f2add(av[m].x, bv[n].x)));
                    acc[m][n] = f2add(acc[m][n], f2abs(f2add(av[m].y, bv[n].y)));
                }
        }
        __syncthreads();
    }

    float* drow = &g_dist[side][0][0];
#pragma unroll
    for (int m = 0; m < 4; m++)
#pragma unroll
        for (int n = 0; n < 4; n++) {
            unsigned long long v = acc[m][n];
            float lo = __uint_as_float((unsigned)v);
            float hi = __uint_as_float((unsigned)(v >> 32));
            drow[(long long)(bm + ty + 16 * m) * NB + (bn + tx + 16 * n)] = lo + hi;
        }
}

// ---------- pass 2: exact top-64 (smallest) via 4x8-bit radix select ----------
__global__ void topk_kernel()
{
    const int row  = blockIdx.x;
    const int side = blockIdx.y;
    const unsigned* __restrict__ urow = (const unsigned*)g_dist[side][row];

    __shared__ int hist[256];
    __shared__ int s_bucket, s_cum;
    const int tid  = threadIdx.x;
    const int lane = tid & 31;

    unsigned prefix = 0;
    int remaining = KSEL;

    for (int pass = 0; pass < 4; pass++) {
        const int shift = 24 - 8 * pass;
        hist[tid] = 0;
        __syncthreads();
        for (int j = tid; j < NB; j += 256) {
            unsigned v = urow[j];
            bool ok = (pass == 0) || ((v >> (shift + 8)) == prefix);
            unsigned mask = __ballot_sync(0xffffffffu, ok);
            if (ok) {
                int b = (v >> shift) & 255;
                unsigned mm = __match_any_sync(mask, b);
                int leader = __ffs(mm) - 1;
                if (lane == leader) atomicAdd(&hist[b], __popc(mm));
            }
        }
        __syncthreads();
        if (tid == 0) {
            int cum = 0, b = 0;
            for (; b < 255; b++) {
                if (cum + hist[b] >= remaining) break;
                cum += hist[b];
            }
            s_bucket = b; s_cum = cum;
        }
        __syncthreads();
        remaining -= s_cum;
        prefix = (prefix << 8) | (unsigned)s_bucket;
    }

    const unsigned T = prefix;      // bit pattern of the 64th-smallest value
    const int need  = remaining;    // how many equal-to-T entries we take

    __shared__ int c_less, c_eq;
    __shared__ int eqi[64];
    if (tid == 0) { c_less = 0; c_eq = 0; }
    __syncthreads();

    int* outp = g_neg[side][row];
    for (int j = tid; j < NB; j += 256) {
        unsigned v = urow[j];
        if (v < T) {
            outp[atomicAdd(&c_less, 1)] = j;
        } else if (v == T) {
            int p = atomicAdd(&c_eq, 1);
            if (p < 64) eqi[p] = j;
        }
    }
    __syncthreads();
    if (tid == 0) {
        int ne = c_eq < 64 ? c_eq : 64;
        int base = c_less;
        for (int s = 0; s < need; s++) {          // smallest indices first (stable argsort tie rule)
            int best = 0x7fffffff, bi = 0;
            for (int t = 0; t < ne; t++)
                if (eqi[t] < best) { best = eqi[t]; bi = t; }
            outp[base + s] = best;
            eqi[bi] = 0x7fffffff;
        }
    }
}

// ---------- pass 3: weighted ranking loss per anchor ----------
__global__ void loss_kernel(const float* __restrict__ out1, const float* __restrict__ out2,
                            const float* __restrict__ ot,
                            const int* __restrict__ a1i, const int* __restrict__ a2i)
{
    const int i = blockIdx.x;
    const int tid = threadIdx.x, lane = tid & 31, w = tid >> 5;

    __shared__ float a1s[DIM], a2s[DIM];
    __shared__ float red[8];
    __shared__ float Dm_s;

    const int ia1 = a1i[i], ia2 = a2i[i];
    if (tid < DIM) {
        a1s[tid] = out1[(long long)ia1 * DIM + tid];
        a2s[tid] = out2[(long long)ia2 * DIM + tid];
    }
    __syncthreads();

    float p = (tid < DIM) ? fabsf(a1s[tid] - a2s[tid]) : 0.0f;
#pragma unroll
    for (int o = 16; o; o >>= 1) p += __shfl_xor_sync(0xffffffffu, p, o);
    if (lane == 0) red[w] = p;
    __syncthreads();
    if (tid == 0) {
        float s = 0.0f;
        for (int k = 0; k < 8; k++) s += red[k];
        Dm_s = s + 1.0f;  // MARGIN
    }
    __syncthreads();
    const float Dm = Dm_s;

    float wsum = 0.0f;
    for (int t = w; t < 2 * KSEL; t += 8) {
        const int side = t >> 6, s = t & 63;
        const int j = g_neg[side][i][s];
        float sm = 0.0f;
        if (side == 0) {
            float wgt = ot[(long long)ia1 * NB + j];
            for (int d = lane; d < DIM; d += 32)
                sm += fabsf(a1s[d] - wgt * out2[(long long)j * DIM + d]);
        } else {
            float wgt = ot[(long long)j * NB + ia2];
            for (int d = lane; d < DIM; d += 32)
                sm += fabsf(a2s[d] - wgt * out1[(long long)j * DIM + d]);
        }
#pragma unroll
        for (int o = 16; o; o >>= 1) sm += __shfl_xor_sync(0xffffffffu, sm, o);
        if (lane == 0) wsum += fmaxf(Dm - sm, 0.0f);
    }
    if (lane == 0) red[w] = wsum;
    __syncthreads();
    if (tid == 0) {
        float s = 0.0f;
        for (int k = 0; k < 8; k++) s += red[k];
        g_partial[i] = s;
    }
}

// ---------- pass 4: deterministic final reduction ----------
__global__ void final_kernel(float* __restrict__ outp)
{
    __shared__ float sh[256];
    const int tid = threadIdx.x;
    float s = 0.0f;
    for (int i = tid; i < NA; i += 256) s += g_partial[i];
    sh[tid] = s;
    __syncthreads();
    for (int o = 128; o; o >>= 1) {
        if (tid < o) sh[tid] += sh[tid + o];
        __syncthreads();
    }
    if (tid == 0) outp[0] = sh[0] * (1.0f / ((float)NA * (float)KSEL));
}

extern "C" void kernel_launch(void* const* d_in, const int* in_sizes, int n_in,
                              void* d_out, int out_size)
{
    const float* out1 = (const float*)d_in[0];
    const float* out2 = (const float*)d_in[1];
    const float* ot   = (const float*)d_in[2];
    const int*   a1   = (const int*)d_in[3];
    const int*   a2   = (const int*)d_in[4];
    float* outp = (float*)d_out;

    dim3 cgrid(NB / BN, NA / BM, 2);
    cdist_kernel<<<cgrid, 256>>>(out1, out2, a1, a2);
    topk_kernel<<<dim3(NA, 2), 256>>>();
    loss_kernel<<<NA, 256>>>(out1, out2, ot, a1, a2);
    final_kernel<<<1, 256>>>(outp);
}